// round 15
// baseline (speedup 1.0000x reference)
#include <cuda_runtime.h>

// out = outer(w, x) @ x0 + bias + x  ==  w * dot(x, x0) + bias + x
// D = 8192 floats = 2048 float4.
// TERMINAL FORM (best measured 6.24us; ncu kernel dur 5.408us, reproduced
// across 3 compilations): 8 CTAs x 256 threads, single launch, one barrier.
// Each CTA redundantly computes the full dot (no inter-CTA dependency, no
// global scratch round-trip). All loads front-batched (19 independent
// LDG.128 -> one memory latency at full MLP). 5-shfl warp reduction; 8 warp
// sums broadcast-folded via 2x LDS.128.
//
// Session evidence: structural perturbations (1/8/16 CTAs; 128/256/512/1024
// threads; packed f32x2; truncated shuffle; load elimination; 2-kernel split)
// measured 6.56-6.91us; identical-binary rerun spread is +-0.3us, so all
// non-regression variants were noise. Wall time is dominated by a fixed
// launch/replay floor (~T_ovh 5000 cyc at un-ramped clocks); this kernel sits
// at the measured minimum of the controllable per-CTA term.

#define NCTAS 8
#define NTHR  256
#define NWARP (NTHR / 32)
#define V4_TOTAL 2048
#define V4_PER_T (V4_TOTAL / NTHR)    // 8
#define V4_PER_CTA (V4_TOTAL / NCTAS) // 256

__global__ void __launch_bounds__(NTHR) cross_fused_kernel(const float4* __restrict__ x0,
                                                           const float4* __restrict__ x,
                                                           const float4* __restrict__ w,
                                                           const float4* __restrict__ b,
                                                           float4* __restrict__ out) {
    const int t = threadIdx.x;

    // ---- Front-batch ALL loads (19 independent LDG.128) ----
    float4 a[V4_PER_T], xv[V4_PER_T];
    #pragma unroll
    for (int k = 0; k < V4_PER_T; k++) {
        a[k]  = x0[t + k * NTHR];
        xv[k] = x[t + k * NTHR];
    }
    const int ei = blockIdx.x * V4_PER_CTA + t;
    float4 wv = w[ei];
    float4 bv = b[ei];
    float4 xe = x[ei];

    // Epilogue additive part is independent of the reduction — fold early.
    float4 cv;
    cv.x = bv.x + xe.x;
    cv.y = bv.y + xe.y;
    cv.z = bv.z + xe.z;
    cv.w = bv.w + xe.w;

    // ---- Partial dot ----
    float s = 0.f;
    #pragma unroll
    for (int k = 0; k < V4_PER_T; k++) {
        s += a[k].x * xv[k].x + a[k].y * xv[k].y
           + a[k].z * xv[k].z + a[k].w * xv[k].w;
    }

    // Warp reduction (5 shfl)
    #pragma unroll
    for (int o = 16; o > 0; o >>= 1)
        s += __shfl_xor_sync(0xFFFFFFFFu, s, o);

    __shared__ float4 ws4[NWARP / 4];   // 8 warp sums as 2 float4 for LDS.128
    float* ws = (float*)ws4;
    const int warp = t >> 5;
    const int lane = t & 31;
    if (lane == 0) ws[warp] = s;
    __syncthreads();

    // Every thread: broadcast-load all 8 warp sums (2x LDS.128), sum locally.
    float4 u0 = ws4[0];
    float4 u1 = ws4[1];
    const float sv = ((u0.x + u0.y) + (u0.z + u0.w))
                   + ((u1.x + u1.y) + (u1.z + u1.w));

    // ---- Epilogue: out = w*s + (b + x) ----
    float4 o;
    o.x = fmaf(wv.x, sv, cv.x);
    o.y = fmaf(wv.y, sv, cv.y);
    o.z = fmaf(wv.z, sv, cv.z);
    o.w = fmaf(wv.w, sv, cv.w);
    out[ei] = o;
}

extern "C" void kernel_launch(void* const* d_in, const int* in_sizes, int n_in,
                              void* d_out, int out_size) {
    const float4* x0 = (const float4*)d_in[0];
    const float4* x  = (const float4*)d_in[1];
    const float4* w  = (const float4*)d_in[2];
    const float4* b  = (const float4*)d_in[3];
    float4* out = (float4*)d_out;

    cross_fused_kernel<<<NCTAS, NTHR>>>(x0, x, w, b, out);
}